// round 17
// baseline (speedup 1.0000x reference)
#include <cuda_runtime.h>
#include <cuda_bf16.h>
#include <cstdint>
#include <cmath>

#define NG    8192
#define BGRP  16
#define GS    512
#define DIM   768

#define TBM 128
#define TBN 128
#define TBK 64
#define NSTAGE 3
#define STAGE_ELEMS (TBM * TBK)
#define SMEM_BYTES (NSTAGE * 2 * STAGE_ELEMS * 2) // 98304 bytes

#define SCALE_CONST 0.03608439182435161f          // 1/sqrt(768)

#if defined(__CUDA_ARCH__) && __CUDA_ARCH__ >= 900
#define GRID_DEP_SYNC() cudaGridDependencySynchronize()
#else
#define GRID_DEP_SYNC()
#endif

// ---------------- scratch ----------------
__device__ __nv_bfloat16 g_xb  [NG * DIM];
__device__ __nv_bfloat16 g_Wqb [DIM * DIM];
__device__ __nv_bfloat16 g_WkT [DIM * DIM];       // Wk transposed: WkT[e,j]=Wk[j,e]
__device__ __nv_bfloat16 g_Wvb [DIM * DIM];
__device__ __nv_bfloat16 g_Wob [DIM * DIM];
__device__ __nv_bfloat16 g_Wvo [DIM * DIM];       // Wo@Wv
__device__ __nv_bfloat16 g_Mqk [DIM * DIM];       // Mqk[e,d] = sum_j Wk[j,e]Wq[j,d]
__device__ float         g_bvo [DIM];             // Wo@bv
__device__ float         g_vqk [DIM];             // Wq^T bk
__device__ float         g_vkq [DIM];             // Wk^T bq
__device__ float         g_cqk [1];               // bq.bk
__device__ float         g_u   [NG];              // x.(Wq^T bk)
__device__ float         g_w   [NG];              // x.(Wk^T bq)
__device__ __nv_bfloat16 g_T   [NG * DIM];        // x@Mqk^T
__device__ __nv_bfloat16 g_VW  [NG * DIM];        // x@Wvo^T + bvo
__device__ __nv_bfloat16 g_P   [BGRP * GS * GS];  // unnormalized exp-scores
__device__ float         g_rs  [NG];              // per-row exp sums

// ---------------- helpers ----------------
__device__ __forceinline__ unsigned sptr(const void* p) {
    return (unsigned)__cvta_generic_to_shared(p);
}
__device__ __forceinline__ void cpasync16(unsigned s, const void* g) {
    asm volatile("cp.async.cg.shared.global [%0], [%1], 16;\n" :: "r"(s), "l"(g));
}
__device__ __forceinline__ void cp_commit() {
    asm volatile("cp.async.commit_group;\n" ::: "memory");
}
__device__ __forceinline__ void cp_wait1() {
    asm volatile("cp.async.wait_group 1;\n" ::: "memory");
}
__device__ __forceinline__ void ldsm4(unsigned& r0, unsigned& r1, unsigned& r2, unsigned& r3, unsigned a) {
    asm volatile("ldmatrix.sync.aligned.m8n8.x4.shared.b16 {%0,%1,%2,%3}, [%4];\n"
                 : "=r"(r0), "=r"(r1), "=r"(r2), "=r"(r3) : "r"(a));
}
__device__ __forceinline__ void ldsm4t(unsigned& r0, unsigned& r1, unsigned& r2, unsigned& r3, unsigned a) {
    asm volatile("ldmatrix.sync.aligned.m8n8.x4.trans.shared.b16 {%0,%1,%2,%3}, [%4];\n"
                 : "=r"(r0), "=r"(r1), "=r"(r2), "=r"(r3) : "r"(a));
}
__device__ __forceinline__ void mma16816(float* d, const unsigned* a, const unsigned* b) {
    asm volatile(
        "mma.sync.aligned.m16n8k16.row.col.f32.bf16.bf16.f32 "
        "{%0,%1,%2,%3}, {%4,%5,%6,%7}, {%8,%9}, {%0,%1,%2,%3};\n"
        : "+f"(d[0]), "+f"(d[1]), "+f"(d[2]), "+f"(d[3])
        : "r"(a[0]), "r"(a[1]), "r"(a[2]), "r"(a[3]), "r"(b[0]), "r"(b[1]));
}

// ---- cp.async tile issue ----
template<bool TB>
__device__ __forceinline__ void issue_tile(
    const __nv_bfloat16* __restrict__ A, const __nv_bfloat16* __restrict__ B,
    __nv_bfloat16* As, __nv_bfloat16* Bs,
    int row0, int col0, int lda, int ldb, int kt, int tid)
{
#pragma unroll
    for (int i = 0; i < 4; i++) {
        int lin = tid + i * 256;
        int r = lin >> 3, c = lin & 7;
        const __nv_bfloat16* g = A + (long)(row0 + r) * lda + kt * TBK + c * 8;
        cpasync16(sptr(As + r * TBK + ((c ^ (r & 7)) << 3)), g);
    }
    if (!TB) {
#pragma unroll
        for (int i = 0; i < 4; i++) {
            int lin = tid + i * 256;
            int r = lin >> 3, c = lin & 7;
            const __nv_bfloat16* g = B + (long)(col0 + r) * ldb + kt * TBK + c * 8;
            cpasync16(sptr(Bs + r * TBK + ((c ^ (r & 7)) << 3)), g);
        }
    } else {
#pragma unroll
        for (int i = 0; i < 4; i++) {
            int lin = tid + i * 256;
            int r = lin >> 4, c = lin & 15;
            const __nv_bfloat16* g = B + (long)(kt * TBK + r) * ldb + col0 + c * 8;
            cpasync16(sptr(Bs + r * TBN + ((c ^ (r & 7)) << 3)), g);
        }
    }
}

// ---------------------------------------------------------------------------
// Core bf16 GEMM body.
// MODE 0: bf16 C = acc + bias[col]                (VW projection)
// MODE 1: bf16 C = exp((acc+u[r]+w[c]+cq)*scale) diag-masked; rowsum atomics
//         (bias=rowsum slice, X=u slice, rs2=w slice, beta=&cq)
// MODE 2: bf16 C = acc                            (combines / T projection)
// MODE 4: fp32 C = X + beta[0]*(acc/rs2[row] + bias[col])  (final fused)
// ---------------------------------------------------------------------------
template<int MODE, bool TB>
__device__ __forceinline__ void gemm_body(
    const __nv_bfloat16* __restrict__ A, const __nv_bfloat16* __restrict__ B,
    const float* __restrict__ bias, void* __restrict__ Cv,
    int K, int lda, int ldb, int ldc,
    const float* __restrict__ X, const float* __restrict__ beta,
    const float* __restrict__ rs2,
    char* dsm, int row0, int col0)
{
    __nv_bfloat16* As = reinterpret_cast<__nv_bfloat16*>(dsm);
    __nv_bfloat16* Bs = As + NSTAGE * STAGE_ELEMS;

    const int tid  = threadIdx.x;
    const int lane = tid & 31;
    const int wid  = tid >> 5;
    const int wm   = (wid & 1) * 64;
    const int wn   = (wid >> 1) * 32;

    float acc[4][4][4];
#pragma unroll
    for (int i = 0; i < 4; i++)
#pragma unroll
        for (int j = 0; j < 4; j++)
#pragma unroll
            for (int k = 0; k < 4; k++) acc[i][j][k] = 0.f;

    const int ntiles = K / TBK;

    GRID_DEP_SYNC();

    issue_tile<TB>(A, B, As, Bs, row0, col0, lda, ldb, 0, tid);
    cp_commit();
    issue_tile<TB>(A, B, As + STAGE_ELEMS, Bs + STAGE_ELEMS, row0, col0, lda, ldb, 1, tid);
    cp_commit();

    for (int kt = 0; kt < ntiles; kt++) {
        const int stg = kt % NSTAGE;
        cp_wait1();
        __syncthreads();

        if (kt + 2 < ntiles) {
            const int ps = (kt + 2) % NSTAGE;
            issue_tile<TB>(A, B, As + ps * STAGE_ELEMS, Bs + ps * STAGE_ELEMS,
                           row0, col0, lda, ldb, kt + 2, tid);
        }
        cp_commit();

        const __nv_bfloat16* Asb = As + stg * STAGE_ELEMS;
        const __nv_bfloat16* Bsb = Bs + stg * STAGE_ELEMS;

#pragma unroll
        for (int ks = 0; ks < 4; ks++) {
            unsigned aF[4][4], bF[4][2];
#pragma unroll
            for (int mi = 0; mi < 4; mi++) {
                int r = wm + mi * 16 + (lane & 15);
                int c = ks * 2 + (lane >> 4);
                ldsm4(aF[mi][0], aF[mi][1], aF[mi][2], aF[mi][3],
                      sptr(Asb + r * TBK + ((c ^ (r & 7)) << 3)));
            }
            if (!TB) {
#pragma unroll
                for (int nt = 0; nt < 2; nt++) {
                    int r = wn + nt * 16 + (lane & 15);
                    int c = ks * 2 + (lane >> 4);
                    unsigned r0, r1, r2, r3;
                    ldsm4(r0, r1, r2, r3,
                          sptr(Bsb + r * TBK + ((c ^ (r & 7)) << 3)));
                    bF[nt * 2 + 0][0] = r0; bF[nt * 2 + 0][1] = r2;
                    bF[nt * 2 + 1][0] = r1; bF[nt * 2 + 1][1] = r3;
                }
            } else {
#pragma unroll
                for (int nt = 0; nt < 2; nt++) {
                    int r = ks * 16 + (lane & 15);
                    int c = (wn >> 3) + nt * 2 + (lane >> 4);
                    unsigned r0, r1, r2, r3;
                    ldsm4t(r0, r1, r2, r3,
                           sptr(Bsb + r * TBN + ((c ^ (r & 7)) << 3)));
                    bF[nt * 2 + 0][0] = r0; bF[nt * 2 + 0][1] = r1;
                    bF[nt * 2 + 1][0] = r2; bF[nt * 2 + 1][1] = r3;
                }
            }
#pragma unroll
            for (int mi = 0; mi < 4; mi++)
#pragma unroll
                for (int nj = 0; nj < 4; nj++)
                    mma16816(acc[mi][nj], aF[mi], bF[nj]);
        }
    }

    // ---------------- epilogue ----------------
    const int rg = lane >> 2;
    const int t  = lane & 3;
    float betav = 0.f;
    if (MODE == 4) betav = beta[0];
    float cq = 0.f;
    if (MODE == 1) cq = beta[0];

    float rsum[4][2];
    if (MODE == 1) {
#pragma unroll
        for (int i = 0; i < 4; i++) { rsum[i][0] = 0.f; rsum[i][1] = 0.f; }
    }

#pragma unroll
    for (int mi = 0; mi < 4; mi++) {
        float inv0 = 0.f, inv1 = 0.f;
        float ur0 = 0.f, ur1 = 0.f;
        const int rr = row0 + wm + mi * 16 + rg;
        if (MODE == 4) {
            inv0 = 1.f / rs2[rr];
            inv1 = 1.f / rs2[rr + 8];
        }
        if (MODE == 1) {
            ur0 = X[rr] + cq;
            ur1 = X[rr + 8] + cq;
        }
#pragma unroll
        for (int nj = 0; nj < 4; nj++) {
            const int r = rr;
            const int c = col0 + wn + nj * 8 + t * 2;
            const float d0 = acc[mi][nj][0];
            const float d1 = acc[mi][nj][1];
            const float d2 = acc[mi][nj][2];
            const float d3 = acc[mi][nj][3];

            if (MODE == 0) {
                __nv_bfloat16* C = reinterpret_cast<__nv_bfloat16*>(Cv);
                const float2 bb = *reinterpret_cast<const float2*>(bias + c);
                *reinterpret_cast<__nv_bfloat162*>(C + (long)r * ldc + c) =
                    __floats2bfloat162_rn(d0 + bb.x, d1 + bb.y);
                *reinterpret_cast<__nv_bfloat162*>(C + (long)(r + 8) * ldc + c) =
                    __floats2bfloat162_rn(d2 + bb.x, d3 + bb.y);
            } else if (MODE == 1) {
                __nv_bfloat16* C = reinterpret_cast<__nv_bfloat16*>(Cv);
                const float wc0 = rs2[c], wc1 = rs2[c + 1];
                float e0 = (r     == c    ) ? 0.f : __expf((d0 + ur0 + wc0) * SCALE_CONST);
                float e1 = (r     == c + 1) ? 0.f : __expf((d1 + ur0 + wc1) * SCALE_CONST);
                float e2 = (r + 8 == c    ) ? 0.f : __expf((d2 + ur1 + wc0) * SCALE_CONST);
                float e3 = (r + 8 == c + 1) ? 0.f : __expf((d3 + ur1 + wc1) * SCALE_CONST);
                *reinterpret_cast<__nv_bfloat162*>(C + (long)r * ldc + c) =
                    __floats2bfloat162_rn(e0, e1);
                *reinterpret_cast<__nv_bfloat162*>(C + (long)(r + 8) * ldc + c) =
                    __floats2bfloat162_rn(e2, e3);
                rsum[mi][0] += e0 + e1;
                rsum[mi][1] += e2 + e3;
            } else if (MODE == 2) {
                __nv_bfloat16* C = reinterpret_cast<__nv_bfloat16*>(Cv);
                *reinterpret_cast<__nv_bfloat162*>(C + (long)r * ldc + c) =
                    __floats2bfloat162_rn(d0, d1);
                *reinterpret_cast<__nv_bfloat162*>(C + (long)(r + 8) * ldc + c) =
                    __floats2bfloat162_rn(d2, d3);
            } else {  // MODE 4
                float* C = reinterpret_cast<float*>(Cv);
                const float2 bb = *reinterpret_cast<const float2*>(bias + c);
                const float2 x0 = *reinterpret_cast<const float2*>(X + (long)r * ldc + c);
                const float2 x1 = *reinterpret_cast<const float2*>(X + (long)(r + 8) * ldc + c);
                *reinterpret_cast<float2*>(C + (long)r * ldc + c) =
                    make_float2(x0.x + betav * (d0 * inv0 + bb.x),
                                x0.y + betav * (d1 * inv0 + bb.y));
                *reinterpret_cast<float2*>(C + (long)(r + 8) * ldc + c) =
                    make_float2(x1.x + betav * (d2 * inv1 + bb.x),
                                x1.y + betav * (d3 * inv1 + bb.y));
            }
        }
    }

    if (MODE == 1) {
        float* rw = const_cast<float*>(bias);
#pragma unroll
        for (int mi = 0; mi < 4; mi++) {
            float s0 = rsum[mi][0], s1 = rsum[mi][1];
            s0 += __shfl_xor_sync(0xffffffffu, s0, 1);
            s0 += __shfl_xor_sync(0xffffffffu, s0, 2);
            s1 += __shfl_xor_sync(0xffffffffu, s1, 1);
            s1 += __shfl_xor_sync(0xffffffffu, s1, 2);
            if (t == 0) {
                const int r = row0 + wm + mi * 16 + rg;
                atomicAdd(rw + r, s0);
                atomicAdd(rw + r + 8, s1);
            }
        }
    }
}

// ---------------- combines: z=0: Wvo=Wo@Wv, z=1: Mqk=WkT@Wq ----------------
__global__ __launch_bounds__(256, 2)
void hgemm_comb(const __nv_bfloat16* __restrict__ Wob, const __nv_bfloat16* __restrict__ Wvb,
                const __nv_bfloat16* __restrict__ WkT, const __nv_bfloat16* __restrict__ Wqb,
                __nv_bfloat16* __restrict__ Wvo, __nv_bfloat16* __restrict__ Mqk)
{
    extern __shared__ char dsm[];
    const int z = blockIdx.z;
    const __nv_bfloat16* A = (z == 0) ? Wob : WkT;
    const __nv_bfloat16* B = (z == 0) ? Wvb : Wqb;
    __nv_bfloat16* C       = (z == 0) ? Wvo : Mqk;
    gemm_body<2, true>(A, B, nullptr, C, DIM, DIM, DIM, DIM,
                       nullptr, nullptr, nullptr,
                       dsm, blockIdx.y * TBM, blockIdx.x * TBN);
}

// ---------------- projections: z=0: T=xb@Mqk^T, z=1: VW=xb@Wvo^T+bvo ----------------
__global__ __launch_bounds__(256, 2)
void hgemm_proj(const __nv_bfloat16* __restrict__ xb,
                const __nv_bfloat16* __restrict__ Mqk, const __nv_bfloat16* __restrict__ Wvo,
                const float* __restrict__ bvo,
                __nv_bfloat16* __restrict__ T, __nv_bfloat16* __restrict__ VW)
{
    extern __shared__ char dsm[];
    const int z = blockIdx.z;
    if (z == 0) {
        gemm_body<2, false>(xb, Mqk, nullptr, T, DIM, DIM, DIM, DIM,
                            nullptr, nullptr, nullptr,
                            dsm, blockIdx.y * TBM, blockIdx.x * TBN);
    } else {
        gemm_body<0, false>(xb, Wvo, bvo, VW, DIM, DIM, DIM, DIM,
                            nullptr, nullptr, nullptr,
                            dsm, blockIdx.y * TBM, blockIdx.x * TBN);
    }
}

// ---------------- generic batched GEMM (z = group) ----------------
template<int MODE, bool TB>
__global__ __launch_bounds__(256, 2)
void hgemm(const __nv_bfloat16* __restrict__ A, const __nv_bfloat16* __restrict__ B,
           const float* __restrict__ bias, void* __restrict__ Cv,
           int K, int lda, int ldb, int ldc,
           long sA, long sB, long sC,
           const float* __restrict__ X, const float* __restrict__ beta,
           const float* __restrict__ rs)
{
    extern __shared__ char dsm[];
    const int bz = blockIdx.z;
    void* C;
    if (MODE == 4) C = (void*)((float*)Cv + bz * sC);
    else           C = (void*)((__nv_bfloat16*)Cv + bz * sC);
    const float* b  = (MODE == 1) ? bias + (long)bz * GS : bias;
    const float* Xb = X;
    const float* rb = rs;
    if (MODE == 1) { Xb = X + (long)bz * GS; rb = rs + (long)bz * GS; }
    if (MODE == 4) { Xb = X + bz * sC;       rb = rs + (long)bz * GS; }
    gemm_body<MODE, TB>(A + bz * sA, B + bz * sB, b, C,
                        K, lda, ldb, ldc, Xb, beta, rb,
                        dsm, blockIdx.y * TBM, blockIdx.x * TBN);
}

// ------- converts (Wk transposed) + rowsum zero + bvo/vqk/vkq/cqk -------
__global__ __launch_bounds__(256)
void conv_all(const float* __restrict__ x,
              const float* __restrict__ wq, const float* __restrict__ wk,
              const float* __restrict__ wv, const float* __restrict__ wo,
              const float* __restrict__ bq, const float* __restrict__ bk,
              const float* __restrict__ bv,
              __nv_bfloat16* __restrict__ xb,
              __nv_bfloat16* __restrict__ wqb, __nv_bfloat16* __restrict__ wkT,
              __nv_bfloat16* __restrict__ wvb, __nv_bfloat16* __restrict__ wob,
              float* __restrict__ rowsum, float* __restrict__ bvo,
              float* __restrict__ vqk, float* __restrict__ vkq,
              float* __restrict__ cqk)
{
    GRID_DEP_SYNC();
    long gid = (long)blockIdx.x * 256 + threadIdx.x;
    if (gid < NG) rowsum[gid] = 0.f;

    long wg = gid >> 5;
    const int lane = threadIdx.x & 31;
    if (wg < DIM) {
        // bvo[wg] = Wo[wg,:].bv
        float s = 0.f;
        for (int d = lane; d < DIM; d += 32) s += wo[wg * DIM + d] * bv[d];
#pragma unroll
        for (int o = 16; o; o >>= 1) s += __shfl_xor_sync(0xffffffffu, s, o);
        if (lane == 0) bvo[wg] = s;
    } else if (wg < DIM + 24) {
        // vqk[d0+lane] = sum_j Wq[j,d0+lane]*bk[j], coalesced over lanes
        int d = (int)(wg - DIM) * 32 + lane;
        float s = 0.f;
#pragma unroll 8
        for (int j = 0; j < DIM; j++) s += wq[(long)j * DIM + d] * bk[j];
        vqk[d] = s;
    } else if (wg < DIM + 48) {
        int d = (int)(wg - DIM - 24) * 32 + lane;
        float s = 0.f;
#pragma unroll 8
        for (int j = 0; j < DIM; j++) s += wk[(long)j * DIM + d] * bq[j];
        vkq[d] = s;
    } else if (wg == DIM + 48) {
        float s = 0.f;
        for (int j = lane; j < DIM; j += 32) s += bq[j] * bk[j];
#pragma unroll
        for (int o = 16; o; o >>= 1) s += __shfl_xor_sync(0xffffffffu, s, o);
        if (lane == 0) cqk[0] = s;
    }

    const long NX = (long)NG * DIM;
    const long W  = (long)DIM * DIM;
    long i = gid * 4;
    if (i >= NX + 4 * W) return;
    if (i < NX) {
        float4 v = *reinterpret_cast<const float4*>(x + i);
        *reinterpret_cast<__nv_bfloat162*>(xb + i)     = __floats2bfloat162_rn(v.x, v.y);
        *reinterpret_cast<__nv_bfloat162*>(xb + i + 2) = __floats2bfloat162_rn(v.z, v.w);
        return;
    }
    long j = i - NX;
    int w = (int)(j / W);
    long off = j - (long)w * W;
    if (w == 1) {
        // transposed store: wkT[d*DIM + row] = Wk[row, d]
        float4 v = *reinterpret_cast<const float4*>(wk + off);
        long row = off / DIM, d = off % DIM;
        wkT[(d + 0) * DIM + row] = __float2bfloat16_rn(v.x);
        wkT[(d + 1) * DIM + row] = __float2bfloat16_rn(v.y);
        wkT[(d + 2) * DIM + row] = __float2bfloat16_rn(v.z);
        wkT[(d + 3) * DIM + row] = __float2bfloat16_rn(v.w);
        return;
    }
    const float* src = (w == 0) ? wq : (w == 2) ? wv : wo;
    __nv_bfloat16* dst = (w == 0) ? wqb : (w == 2) ? wvb : wob;
    float4 v = *reinterpret_cast<const float4*>(src + off);
    *reinterpret_cast<__nv_bfloat162*>(dst + off)     = __floats2bfloat162_rn(v.x, v.y);
    *reinterpret_cast<__nv_bfloat162*>(dst + off + 2) = __floats2bfloat162_rn(v.z, v.w);
}

// ------- u/w: warp-per-row dots of xb with vqk/vkq -------
__global__ __launch_bounds__(256)
void uvw_kernel(const __nv_bfloat16* __restrict__ xb,
                const float* __restrict__ vqk, const float* __restrict__ vkq,
                float* __restrict__ u, float* __restrict__ w)
{
    GRID_DEP_SYNC();
    const int row  = blockIdx.x * 8 + (threadIdx.x >> 5);
    const int lane = threadIdx.x & 31;
    const __nv_bfloat16* xr = xb + (long)row * DIM;
    float su = 0.f, sw = 0.f;
#pragma unroll
    for (int it = 0; it < 3; it++) {
        const int d = it * 256 + lane * 8;
        uint4 raw = *reinterpret_cast<const uint4*>(xr + d);
        const unsigned ww[4] = {raw.x, raw.y, raw.z, raw.w};
        const float4 q0 = *reinterpret_cast<const float4*>(vqk + d);
        const float4 q1 = *reinterpret_cast<const float4*>(vqk + d + 4);
        const float4 k0 = *reinterpret_cast<const float4*>(vkq + d);
        const float4 k1 = *reinterpret_cast<const float4*>(vkq + d + 4);
        float xv[8];
#pragma unroll
        for (int p = 0; p < 4; p++) {
            float2 f2 = __bfloat1622float2(*reinterpret_cast<const __nv_bfloat162*>(&ww[p]));
            xv[2 * p] = f2.x; xv[2 * p + 1] = f2.y;
        }
        su += xv[0]*q0.x + xv[1]*q0.y + xv[2]*q0.z + xv[3]*q0.w
            + xv[4]*q1.x + xv[5]*q1.y + xv[6]*q1.z + xv[7]*q1.w;
        sw += xv[0]*k0.x + xv[1]*k0.y + xv[2]*k0.z + xv[3]*k0.w
            + xv[4]*k1.x + xv[5]*k1.y + xv[6]*k1.z + xv[7]*k1.w;
    }
#pragma unroll
    for (int o = 16; o; o >>= 1) {
        su += __shfl_xor_sync(0xffffffffu, su, o);
        sw += __shfl_xor_sync(0xffffffffu, sw, o);
    }
    if (lane == 0) { u[row] = su; w[row] = sw; }
}

// ---------------------------------------------------------------------------
// Launcher. 6 PDL-linked kernels:
//   conv -> combine(Wvo,Mqk) -> uvw -> proj(T,VW) -> scores(exp+rowsum) -> final
// ---------------------------------------------------------------------------
extern "C" void kernel_launch(void* const* d_in, const int* in_sizes, int n_in,
                              void* d_out, int out_size)
{
    (void)in_sizes; (void)n_in; (void)out_size;
    const float* x    = (const float*)d_in[0];
    const float* Wq   = (const float*)d_in[2];
    const float* bq   = (const float*)d_in[3];
    const float* Wk   = (const float*)d_in[4];
    const float* bk   = (const float*)d_in[5];
    const float* Wv   = (const float*)d_in[6];
    const float* bv   = (const float*)d_in[7];
    const float* Wo   = (const float*)d_in[8];
    const float* bo   = (const float*)d_in[9];
    const float* beta = (const float*)d_in[10];
    float* out = (float*)d_out;

    __nv_bfloat16 *xb, *Wqb, *WkT, *Wvb, *Wob, *Wvo, *Mqk, *T, *VW, *P;
    float *RS, *BVO, *VQK, *VKQ, *CQK, *U, *Wvec;
    cudaGetSymbolAddress((void**)&xb,  g_xb);
    cudaGetSymbolAddress((void**)&Wqb, g_Wqb);
    cudaGetSymbolAddress((void**)&WkT, g_WkT);
    cudaGetSymbolAddress((void**)&Wvb, g_Wvb);
    cudaGetSymbolAddress((void**)&Wob, g_Wob);
    cudaGetSymbolAddress((void**)&Wvo, g_Wvo);
    cudaGetSymbolAddress((void**)&Mqk, g_Mqk);
    cudaGetSymbolAddress((void**)&T,   g_T);
    cudaGetSymbolAddress((void**)&VW,  g_VW);
    cudaGetSymbolAddress((void**)&P,   g_P);
    cudaGetSymbolAddress((void**)&RS,  g_rs);
    cudaGetSymbolAddress((void**)&BVO, g_bvo);
    cudaGetSymbolAddress((void**)&VQK, g_vqk);
    cudaGetSymbolAddress((void**)&VKQ, g_vkq);
    cudaGetSymbolAddress((void**)&CQK, g_cqk);
    cudaGetSymbolAddress((void**)&U,   g_u);
    cudaGetSymbolAddress((void**)&Wvec, g_w);

    static bool init_done = false;
    if (!init_done) {
        cudaFuncSetAttribute(hgemm_comb,      cudaFuncAttributeMaxDynamicSharedMemorySize, SMEM_BYTES);
        cudaFuncSetAttribute(hgemm_proj,      cudaFuncAttributeMaxDynamicSharedMemorySize, SMEM_BYTES);
        cudaFuncSetAttribute(hgemm<1, false>, cudaFuncAttributeMaxDynamicSharedMemorySize, SMEM_BYTES);
        cudaFuncSetAttribute(hgemm<4, true>,  cudaFuncAttributeMaxDynamicSharedMemorySize, SMEM_BYTES);
        init_done = true;
    }

    cudaLaunchAttribute pdl[1];
    pdl[0].id = cudaLaunchAttributeProgrammaticStreamSerialization;
    pdl[0].val.programmaticStreamSerializationAllowed = 1;

    auto mkcfg = [&](dim3 g, dim3 b, size_t sm) {
        cudaLaunchConfig_t cfg{};
        cfg.gridDim = g;
        cfg.blockDim = b;
        cfg.dynamicSmemBytes = sm;
        cfg.stream = 0;
        cfg.attrs = pdl;
        cfg.numAttrs = 1;
        return cfg;
    };

    // converts + aux vectors
    {
        long total4 = ((long)NG * DIM + 4L * DIM * DIM) / 4;
        int blocks = (int)((total4 + 255) / 256);
        cudaLaunchConfig_t cfg = mkcfg(dim3(blocks), dim3(256), 0);
        cudaLaunchKernelEx(&cfg, conv_all, x, Wq, Wk, Wv, Wo, bq, bk, bv,
                           xb, Wqb, WkT, Wvb, Wob, RS, BVO, VQK, VKQ, CQK);
    }

    // combines: Wvo = Wo@Wv, Mqk = WkT@Wq
    {
        cudaLaunchConfig_t cfg = mkcfg(dim3(6, 6, 2), dim3(256), SMEM_BYTES);
        cudaLaunchKernelEx(&cfg, hgemm_comb,
                           (const __nv_bfloat16*)Wob, (const __nv_bfloat16*)Wvb,
                           (const __nv_bfloat16*)WkT, (const __nv_bfloat16*)Wqb,
                           Wvo, Mqk);
    }

    // u/w vectors
    {
        cudaLaunchConfig_t cfg = mkcfg(dim3(NG / 8), dim3(256), 0);
        cudaLaunchKernelEx(&cfg, uvw_kernel, (const __nv_bfloat16*)xb,
                           (const float*)VQK, (const float*)VKQ, U, Wvec);
    }

    // projections: T = xb@Mqk^T, VW = xb@Wvo^T + bvo
    {
        cudaLaunchConfig_t cfg = mkcfg(dim3(6, 64, 2), dim3(256), SMEM_BYTES);
        cudaLaunchKernelEx(&cfg, hgemm_proj, (const __nv_bfloat16*)xb,
                           (const __nv_bfloat16*)Mqk, (const __nv_bfloat16*)Wvo,
                           (const float*)BVO, T, VW);
    }

    // scores: P_g = exp(scale*(T_g@xb_g^T + u + w + c)) masked, bf16
    {
        cudaLaunchConfig_t cfg = mkcfg(dim3(4, 4, BGRP), dim3(256), SMEM_BYTES);
        cudaLaunchKernelEx(&cfg, hgemm<1, false>,
                           (const __nv_bfloat16*)T, (const __nv_bfloat16*)xb,
                           (const float*)RS, (void*)P,
                           DIM, DIM, DIM, GS,
                           (long)GS * DIM, (long)GS * DIM, (long)GS * GS,
                           (const float*)U, (const float*)CQK, (const float*)Wvec);
    }

    // final: out = x + beta*((P_g @ VW_g)/rs + bo)
    {
        cudaLaunchConfig_t cfg = mkcfg(dim3(6, 4, BGRP), dim3(256), SMEM_BYTES);
        cudaLaunchKernelEx(&cfg, hgemm<4, true>,
                           (const __nv_bfloat16*)P, (const __nv_bfloat16*)VW,
                           bo, (void*)out,
                           GS, GS, DIM, DIM,
                           (long)GS * GS, (long)GS * DIM, (long)GS * DIM,
                           x, beta, (const float*)RS);
    }
}